// round 14
// baseline (speedup 1.0000x reference)
#include <cuda_runtime.h>

// Kobayashi dendrite growth, single timestep.
// Register-resident y-sweep, warp-shuffle x-exchange, zero shared memory.
// phi main rows: TWO-iteration prefetch (covers 577cyc DRAM first-touch);
// tempr/halo rows: one-iteration prefetch. Grid/time scales folded into
// aniso outputs via sqrt-scaling. B=4, H=W=2048, periodic, fp32.
// Output: [phi_new | tempr_new].

#define Wd 2048
#define Hd 2048
#define MASK 2047
#define BATCH 4
#define VY 16          // rows per warp strip
#define NWARP 4        // warps per block

// Derived/folded constants:
//  SQ    = sqrt(INVDX2*DTTAU) = sqrt(1111.1111/3)           = 19.24500897
//  EPSBS = EPSB*SQ            = 0.1924501
//  EB_DS = EPSB*DELTA*SQ      = 3.849002e-3
//  EDC2b = (-EPSB*ANISO*DELTA)*C_CROSS*DTTAU/SQ             = -5.7735027e-3
//  APIXT = (ALPHA/pi)*DTTAU                                 = 0.09549297
//  MB    = -0.5*DTTAU                                       = -0.16666667
//  DTCI  = DT*INVDX2                                        = 0.11111111
#define C6T0   0.3623577545f  // cos(6*0.2)
#define S6T0   0.9320390860f  // sin(6*0.2)
#define EPSBS  0.1924501f
#define EB_DS  3.849002e-3f
#define EDC2b  (-5.7735027e-3f)
#define APIXT  0.09549297f
#define MB     (-0.16666667f)
#define DTTAU  (1.0f/3.0f)
#define DTCI   0.11111111f
#define KAPPA_ 1.8f
#define GAMMA_ 10.0f
#define TEQ_   1.0f
#define PIO2   1.5707963268f
#define R2PAD  1e-30f

#define FULLM 0xffffffffu

// From raw (unscaled) central differences produce the pre-scaled
//  p1 = epsS*sinA*EDC2b*gx, p2 = -epsS*sinA*EDC2b*gy, e2 = epsS^2
__device__ __forceinline__ void aniso(float gx, float gy,
                                      float& p1, float& p2, float& e2)
{
    float r2 = fmaf(gx, gx, fmaf(gy, gy, R2PAD));
    float inv = rsqrtf(r2);
    float c = gx * inv, s = gy * inv;
    float x2 = c * c;
    float c6 = fmaf(fmaf(fmaf(x2, 32.0f, -48.0f), x2, 18.0f), x2, -1.0f);
    float s6 = (s * c) * fmaf(fmaf(x2, 32.0f, -32.0f), x2, 6.0f);
    float cosA = fmaf(c6, C6T0, s6 * S6T0);
    float sinA = fmaf(s6, C6T0, -c6 * S6T0);
    float epsS = fmaf(cosA, EB_DS, EPSBS);
    float ee   = epsS * (sinA * EDC2b);
    p1 = ee * gx;
    p2 = -ee * gy;
    e2 = epsS * epsS;
}

// Strip-edge halo column: only p2 needed (same scaling).
__device__ __forceinline__ float aniso_p2(float gx, float gy)
{
    float r2 = fmaf(gx, gx, fmaf(gy, gy, R2PAD));
    float inv = rsqrtf(r2);
    float c = gx * inv, s = gy * inv;
    float x2 = c * c;
    float c6 = fmaf(fmaf(fmaf(x2, 32.0f, -48.0f), x2, 18.0f), x2, -1.0f);
    float s6 = (s * c) * fmaf(fmaf(x2, 32.0f, -32.0f), x2, 6.0f);
    float cosA = fmaf(c6, C6T0, s6 * S6T0);
    float sinA = fmaf(s6, C6T0, -c6 * S6T0);
    float epsS = fmaf(cosA, EB_DS, EPSBS);
    return -(epsS * (sinA * EDC2b)) * gy;
}

// atan for z >= 0 (arg is GAMMA*(1-T), T in [0,1)). Minimax, err ~2e-7.
__device__ __forceinline__ float atan_pos(float z)
{
    float t = fminf(z, __fdividef(1.0f, z));
    float x2 = t * t;
    float p = fmaf(x2, -0.0117212f, 0.05265332f);
    p = fmaf(p, x2, -0.11643287f);
    p = fmaf(p, x2,  0.19354346f);
    p = fmaf(p, x2, -0.33262347f);
    p = fmaf(p, x2,  0.99997726f);
    p *= t;
    return (z > 1.0f) ? (PIO2 - p) : p;
}

__global__ __launch_bounds__(NWARP * 32, 4)
void dendrite_kernel(const float* __restrict__ phi,
                     const float* __restrict__ tempr,
                     float* __restrict__ out_phi,
                     float* __restrict__ out_tmp)
{
    const int lane = threadIdx.x & 31;
    const int warp = threadIdx.x >> 5;
    const int x0 = blockIdx.x * 128;
    const int y0 = (blockIdx.y * NWARP + warp) * VY;
    const int base = (int)blockIdx.z * (Hd * Wd);
    const float* Pp = phi + base;
    const float* Tp = tempr + base;

    const int xc = x0 + lane * 4;
    const bool eL = (lane == 0);
    const bool eR = (lane == 31);
    const bool edge = eL || eR;
    const int xh2 = eL ? ((x0 - 2) & MASK) : ((x0 + 128) & MASK);
    const int xh1 = eL ? ((x0 - 1) & MASK) : ((x0 + 128) & MASK);

    auto ldP4 = [&](int y) -> float4 {
        return *(const float4*)(Pp + ((y & MASK) << 11) + xc);
    };
    auto ldT4 = [&](int y) -> float4 {
        return *(const float4*)(Tp + ((y & MASK) << 11) + xc);
    };
    auto ldPH = [&](int y) -> float2 {
        float2 h = make_float2(1.0f, 1.0f);
        if (edge) h = *(const float2*)(Pp + ((y & MASK) << 11) + xh2);
        return h;
    };
    auto ldTH = [&](int y) -> float {
        float s = 0.0f;
        if (edge) s = Tp[((y & MASK) << 11) + xh1];
        return s;
    };

    // aniso over one row; h2 = halo-column p2; plc/prc = the center row's
    // left/right phi neighbors (re-used by the output stage next iteration).
    auto aniso_row = [&](const float4& pm, const float4& pc, const float4& pp,
                         const float2& hm, const float2& hc, const float2& hp,
                         float4& q1, float4& q2, float4& e2v, float& h2,
                         float& plc, float& prc)
    {
        float pl = __shfl_up_sync(FULLM, pc.w, 1);
        if (eL) pl = hc.y;
        float pr = __shfl_down_sync(FULLM, pc.x, 1);
        if (eR) pr = hc.x;
        aniso(pc.y - pl,   pp.x - pm.x, q1.x, q2.x, e2v.x);
        aniso(pc.z - pc.x, pp.y - pm.y, q1.y, q2.y, e2v.y);
        aniso(pc.w - pc.y, pp.z - pm.z, q1.z, q2.z, e2v.z);
        aniso(pr - pc.z,   pp.w - pm.w, q1.w, q2.w, e2v.w);
        float gxh = eL ? (pc.x - hc.x) : (hc.y - pc.w);
        float gyh = eL ? (hp.y - hm.y) : (hp.x - hm.x);
        h2 = aniso_p2(gxh, gyh);
        plc = pl; prc = pr;
    };

    // ---- prologue: windows for rows y0-1 .. y0+1
    float4 pZ = ldP4(y0 - 2);
    float4 pA = ldP4(y0 - 1);  float2 hA = ldPH(y0 - 1);
    float4 pB = ldP4(y0);      float2 hB = ldPH(y0);
    float4 pC = ldP4(y0 + 1);  float2 hC = ldPH(y0 + 1);
    float4 tA = ldT4(y0 - 1);
    float4 tB = ldT4(y0);      float  sB = ldTH(y0);

    // prefetch pipeline: pD (1 ahead), pE (2 ahead) for phi main rows;
    // hD/tC/sC one ahead.
    float4 pD = ldP4(y0 + 2);  float2 hD = ldPH(y0 + 2);
    float4 pE = ldP4(y0 + 3);
    float4 tC = ldT4(y0 + 1);  float  sC = ldTH(y0 + 1);

    float4 q1A, q2A, e2A; float h2A, plA, prA;   // row y0-1 (only q1A consumed)
    aniso_row(pZ, pA, pB, hA, hA, hA, q1A, q2A, e2A, h2A, plA, prA);
    float4 q1B, q2B, e2B; float h2B, plB, prB;   // row y0
    aniso_row(pA, pB, pC, hA, hB, hC, q1B, q2B, e2B, h2B, plB, prB);

    #pragma unroll 4
    for (int r = y0; r < y0 + VY; ++r) {
        // ---- prefetches: phi main row 2 iterations ahead; halo/tempr 1 ahead.
        //      Tail iterations' extra rows wrap harmlessly.
        float4 pEn = ldP4(r + 4);
        float2 hDn = ldPH(r + 3);
        float4 tCn = ldT4(r + 2);  float  sCn = ldTH(r + 2);

        float4 q1C, q2C, e2C; float h2C, plC, prC;   // row r+1
        aniso_row(pB, pC, pD, hB, hC, hD, q1C, q2C, e2C, h2C, plC, prC);

        // ---- output at row r (pl/pr carried from row r's aniso_row)
        float tl = __shfl_up_sync(FULLM, tB.w, 1);   if (eL) tl = sB;
        float tr = __shfl_down_sync(FULLM, tB.x, 1); if (eR) tr = sB;
        float bl = __shfl_up_sync(FULLM, q2B.w, 1);  if (eL) bl = h2B;
        float br = __shfl_down_sync(FULLM, q2B.x, 1); if (eR) br = h2B;

        // raw 5-point sums; all scales pre-folded into e2/DTCI/tt terms
        float4 lapp, lapt, tt;
        lapp.x = fmaf(-4.0f, pB.x, pA.x + pC.x + plB  + pB.y);
        lapp.y = fmaf(-4.0f, pB.y, pA.y + pC.y + pB.x + pB.z);
        lapp.z = fmaf(-4.0f, pB.z, pA.z + pC.z + pB.y + pB.w);
        lapp.w = fmaf(-4.0f, pB.w, pA.w + pC.w + pB.z + prB );

        lapt.x = fmaf(-4.0f, tB.x, tA.x + tC.x + tl   + tB.y);
        lapt.y = fmaf(-4.0f, tB.y, tA.y + tC.y + tB.x + tB.z);
        lapt.z = fmaf(-4.0f, tB.z, tA.z + tC.z + tB.y + tB.w);
        lapt.w = fmaf(-4.0f, tB.w, tA.w + tC.w + tB.z + tr  );

        tt.x = (q1C.x - q1A.x) + (q2B.y - bl   );
        tt.y = (q1C.y - q1A.y) + (q2B.z - q2B.x);
        tt.z = (q1C.z - q1A.z) + (q2B.w - q2B.y);
        tt.w = (q1C.w - q1A.w) + (br    - q2B.z);

        float4 op, ot;
        {
            float at, g, dphi;
            at = atan_pos(GAMMA_ * (TEQ_ - tB.x));
            g = (pB.x * (1.0f - pB.x)) * fmaf(pB.x, DTTAU, fmaf(at, APIXT, MB));
            dphi = fmaf(e2B.x, lapp.x, tt.x) + g;
            op.x = pB.x + dphi; ot.x = fmaf(KAPPA_, dphi, fmaf(DTCI, lapt.x, tB.x));

            at = atan_pos(GAMMA_ * (TEQ_ - tB.y));
            g = (pB.y * (1.0f - pB.y)) * fmaf(pB.y, DTTAU, fmaf(at, APIXT, MB));
            dphi = fmaf(e2B.y, lapp.y, tt.y) + g;
            op.y = pB.y + dphi; ot.y = fmaf(KAPPA_, dphi, fmaf(DTCI, lapt.y, tB.y));

            at = atan_pos(GAMMA_ * (TEQ_ - tB.z));
            g = (pB.z * (1.0f - pB.z)) * fmaf(pB.z, DTTAU, fmaf(at, APIXT, MB));
            dphi = fmaf(e2B.z, lapp.z, tt.z) + g;
            op.z = pB.z + dphi; ot.z = fmaf(KAPPA_, dphi, fmaf(DTCI, lapt.z, tB.z));

            at = atan_pos(GAMMA_ * (TEQ_ - tB.w));
            g = (pB.w * (1.0f - pB.w)) * fmaf(pB.w, DTTAU, fmaf(at, APIXT, MB));
            dphi = fmaf(e2B.w, lapp.w, tt.w) + g;
            op.w = pB.w + dphi; ot.w = fmaf(KAPPA_, dphi, fmaf(DTCI, lapt.w, tB.w));
        }
        const int o = base + (r << 11) + xc;
        __stcs((float4*)(out_phi + o), op);   // streaming: never re-read
        __stcs((float4*)(out_tmp + o), ot);

        // ---- shift windows (prefetched values become current)
        pA = pB; pB = pC; pC = pD; pD = pE; pE = pEn;
        hB = hC; hC = hD; hD = hDn;
        tA = tB; tB = tC; sB = sC; tC = tCn; sC = sCn;
        q1A = q1B; q1B = q1C;
        q2B = q2C; h2B = h2C; e2B = e2C;
        plB = plC; prB = prC;
    }
}

extern "C" void kernel_launch(void* const* d_in, const int* in_sizes, int n_in,
                              void* d_out, int out_size)
{
    const float* phi   = (const float*)d_in[0];
    const float* tempr = (const float*)d_in[1];
    float* out = (float*)d_out;
    float* out_phi = out;
    float* out_tmp = out + (size_t)BATCH * Hd * Wd;

    dim3 block(NWARP * 32);
    dim3 grid(Wd / 128, Hd / VY / NWARP, BATCH);
    dendrite_kernel<<<grid, block>>>(phi, tempr, out_phi, out_tmp);
}

// round 15
// speedup vs baseline: 1.0995x; 1.0995x over previous
#include <cuda_runtime.h>

// Kobayashi dendrite growth, single timestep.
// Register-resident y-sweep, warp-shuffle x-exchange, zero shared memory,
// one-iteration register prefetch (R12 structure) + L2 software prefetch
// two rows ahead (no register cost). Grid/time scales folded into aniso
// outputs via sqrt-scaling. B=4, H=W=2048, periodic, fp32.
// Output: [phi_new | tempr_new].

#define Wd 2048
#define Hd 2048
#define MASK 2047
#define BATCH 4
#define VY 16          // rows per warp strip
#define NWARP 4        // warps per block

// Derived/folded constants:
//  SQ    = sqrt(INVDX2*DTTAU) = sqrt(1111.1111/3)           = 19.24500897
//  EPSBS = EPSB*SQ            = 0.1924501
//  EB_DS = EPSB*DELTA*SQ      = 3.849002e-3
//  EDC2b = (-EPSB*ANISO*DELTA)*C_CROSS*DTTAU/SQ             = -5.7735027e-3
//  APIXT = (ALPHA/pi)*DTTAU                                 = 0.09549297
//  MB    = -0.5*DTTAU                                       = -0.16666667
//  DTCI  = DT*INVDX2                                        = 0.11111111
#define C6T0   0.3623577545f  // cos(6*0.2)
#define S6T0   0.9320390860f  // sin(6*0.2)
#define EPSBS  0.1924501f
#define EB_DS  3.849002e-3f
#define EDC2b  (-5.7735027e-3f)
#define APIXT  0.09549297f
#define MB     (-0.16666667f)
#define DTTAU  (1.0f/3.0f)
#define DTCI   0.11111111f
#define KAPPA_ 1.8f
#define GAMMA_ 10.0f
#define TEQ_   1.0f
#define PIO2   1.5707963268f
#define R2PAD  1e-30f

#define FULLM 0xffffffffu

// From raw (unscaled) central differences produce the pre-scaled
//  p1 = epsS*sinA*EDC2b*gx, p2 = -epsS*sinA*EDC2b*gy, e2 = epsS^2
__device__ __forceinline__ void aniso(float gx, float gy,
                                      float& p1, float& p2, float& e2)
{
    float r2 = fmaf(gx, gx, fmaf(gy, gy, R2PAD));
    float inv = rsqrtf(r2);
    float c = gx * inv, s = gy * inv;
    float x2 = c * c;
    float c6 = fmaf(fmaf(fmaf(x2, 32.0f, -48.0f), x2, 18.0f), x2, -1.0f);
    float s6 = (s * c) * fmaf(fmaf(x2, 32.0f, -32.0f), x2, 6.0f);
    float cosA = fmaf(c6, C6T0, s6 * S6T0);
    float sinA = fmaf(s6, C6T0, -c6 * S6T0);
    float epsS = fmaf(cosA, EB_DS, EPSBS);
    float ee   = epsS * (sinA * EDC2b);
    p1 = ee * gx;
    p2 = -ee * gy;
    e2 = epsS * epsS;
}

// Strip-edge halo column: only p2 needed (same scaling).
__device__ __forceinline__ float aniso_p2(float gx, float gy)
{
    float r2 = fmaf(gx, gx, fmaf(gy, gy, R2PAD));
    float inv = rsqrtf(r2);
    float c = gx * inv, s = gy * inv;
    float x2 = c * c;
    float c6 = fmaf(fmaf(fmaf(x2, 32.0f, -48.0f), x2, 18.0f), x2, -1.0f);
    float s6 = (s * c) * fmaf(fmaf(x2, 32.0f, -32.0f), x2, 6.0f);
    float cosA = fmaf(c6, C6T0, s6 * S6T0);
    float sinA = fmaf(s6, C6T0, -c6 * S6T0);
    float epsS = fmaf(cosA, EB_DS, EPSBS);
    return -(epsS * (sinA * EDC2b)) * gy;
}

// atan for z >= 0 (arg is GAMMA*(1-T), T in [0,1)). Minimax, err ~2e-7.
__device__ __forceinline__ float atan_pos(float z)
{
    float t = fminf(z, __fdividef(1.0f, z));
    float x2 = t * t;
    float p = fmaf(x2, -0.0117212f, 0.05265332f);
    p = fmaf(p, x2, -0.11643287f);
    p = fmaf(p, x2,  0.19354346f);
    p = fmaf(p, x2, -0.33262347f);
    p = fmaf(p, x2,  0.99997726f);
    p *= t;
    return (z > 1.0f) ? (PIO2 - p) : p;
}

__global__ __launch_bounds__(NWARP * 32, 4)
void dendrite_kernel(const float* __restrict__ phi,
                     const float* __restrict__ tempr,
                     float* __restrict__ out_phi,
                     float* __restrict__ out_tmp)
{
    const int lane = threadIdx.x & 31;
    const int warp = threadIdx.x >> 5;
    const int x0 = blockIdx.x * 128;
    const int y0 = (blockIdx.y * NWARP + warp) * VY;
    const int base = (int)blockIdx.z * (Hd * Wd);
    const float* Pp = phi + base;
    const float* Tp = tempr + base;

    const int xc = x0 + lane * 4;
    const bool eL = (lane == 0);
    const bool eR = (lane == 31);
    const bool edge = eL || eR;
    const int xh2 = eL ? ((x0 - 2) & MASK) : ((x0 + 128) & MASK);
    const int xh1 = eL ? ((x0 - 1) & MASK) : ((x0 + 128) & MASK);

    auto ldP4 = [&](int y) -> float4 {
        return *(const float4*)(Pp + ((y & MASK) << 11) + xc);
    };
    auto ldT4 = [&](int y) -> float4 {
        return *(const float4*)(Tp + ((y & MASK) << 11) + xc);
    };
    auto ldPH = [&](int y) -> float2 {
        float2 h = make_float2(1.0f, 1.0f);
        if (edge) h = *(const float2*)(Pp + ((y & MASK) << 11) + xh2);
        return h;
    };
    auto ldTH = [&](int y) -> float {
        float s = 0.0f;
        if (edge) s = Tp[((y & MASK) << 11) + xh1];
        return s;
    };
    // L2 prefetch: warm DRAM->L2 ahead of the register loads (no data regs).
    auto pfL2 = [&](const float* p, int y) {
        asm volatile("prefetch.global.L2 [%0];"
                     :: "l"(p + ((y & MASK) << 11) + xc));
    };

    // aniso over one row; h2 = halo-column p2; plc/prc = the center row's
    // left/right phi neighbors (re-used by the output stage next iteration).
    auto aniso_row = [&](const float4& pm, const float4& pc, const float4& pp,
                         const float2& hm, const float2& hc, const float2& hp,
                         float4& q1, float4& q2, float4& e2v, float& h2,
                         float& plc, float& prc)
    {
        float pl = __shfl_up_sync(FULLM, pc.w, 1);
        if (eL) pl = hc.y;
        float pr = __shfl_down_sync(FULLM, pc.x, 1);
        if (eR) pr = hc.x;
        aniso(pc.y - pl,   pp.x - pm.x, q1.x, q2.x, e2v.x);
        aniso(pc.z - pc.x, pp.y - pm.y, q1.y, q2.y, e2v.y);
        aniso(pc.w - pc.y, pp.z - pm.z, q1.z, q2.z, e2v.z);
        aniso(pr - pc.z,   pp.w - pm.w, q1.w, q2.w, e2v.w);
        float gxh = eL ? (pc.x - hc.x) : (hc.y - pc.w);
        float gyh = eL ? (hp.y - hm.y) : (hp.x - hm.x);
        h2 = aniso_p2(gxh, gyh);
        plc = pl; prc = pr;
    };

    // ---- prologue: windows for rows y0-1 .. y0+1
    float4 pZ = ldP4(y0 - 2);
    float4 pA = ldP4(y0 - 1);  float2 hA = ldPH(y0 - 1);
    float4 pB = ldP4(y0);      float2 hB = ldPH(y0);
    float4 pC = ldP4(y0 + 1);  float2 hC = ldPH(y0 + 1);
    float4 tA = ldT4(y0 - 1);
    float4 tB = ldT4(y0);      float  sB = ldTH(y0);

    // prefetched values consumed by the FIRST loop iteration
    float4 pD = ldP4(y0 + 2);  float2 hD = ldPH(y0 + 2);
    float4 tC = ldT4(y0 + 1);  float  sC = ldTH(y0 + 1);

    // warm L2 for the first real loads of the loop
    pfL2(Pp, y0 + 3);
    pfL2(Tp, y0 + 2);

    float4 q1A, q2A, e2A; float h2A, plA, prA;   // row y0-1 (only q1A consumed)
    aniso_row(pZ, pA, pB, hA, hA, hA, q1A, q2A, e2A, h2A, plA, prA);
    float4 q1B, q2B, e2B; float h2B, plB, prB;   // row y0
    aniso_row(pA, pB, pC, hA, hB, hC, q1B, q2B, e2B, h2B, plB, prB);

    #pragma unroll 4
    for (int r = y0; r < y0 + VY; ++r) {
        // ---- L2 prefetch one row beyond next iteration's register loads
        pfL2(Pp, r + 4);
        pfL2(Tp, r + 3);

        // ---- register prefetch for NEXT iteration (consumed after shift);
        //      last iteration's extra rows wrap harmlessly.
        float4 pDn = ldP4(r + 3);  float2 hDn = ldPH(r + 3);
        float4 tCn = ldT4(r + 2);  float  sCn = ldTH(r + 2);

        float4 q1C, q2C, e2C; float h2C, plC, prC;   // row r+1
        aniso_row(pB, pC, pD, hB, hC, hD, q1C, q2C, e2C, h2C, plC, prC);

        // ---- output at row r (pl/pr carried from row r's aniso_row)
        float tl = __shfl_up_sync(FULLM, tB.w, 1);   if (eL) tl = sB;
        float tr = __shfl_down_sync(FULLM, tB.x, 1); if (eR) tr = sB;
        float bl = __shfl_up_sync(FULLM, q2B.w, 1);  if (eL) bl = h2B;
        float br = __shfl_down_sync(FULLM, q2B.x, 1); if (eR) br = h2B;

        // raw 5-point sums; all scales pre-folded into e2/DTCI/tt terms
        float4 lapp, lapt, tt;
        lapp.x = fmaf(-4.0f, pB.x, pA.x + pC.x + plB  + pB.y);
        lapp.y = fmaf(-4.0f, pB.y, pA.y + pC.y + pB.x + pB.z);
        lapp.z = fmaf(-4.0f, pB.z, pA.z + pC.z + pB.y + pB.w);
        lapp.w = fmaf(-4.0f, pB.w, pA.w + pC.w + pB.z + prB );

        lapt.x = fmaf(-4.0f, tB.x, tA.x + tC.x + tl   + tB.y);
        lapt.y = fmaf(-4.0f, tB.y, tA.y + tC.y + tB.x + tB.z);
        lapt.z = fmaf(-4.0f, tB.z, tA.z + tC.z + tB.y + tB.w);
        lapt.w = fmaf(-4.0f, tB.w, tA.w + tC.w + tB.z + tr  );

        tt.x = (q1C.x - q1A.x) + (q2B.y - bl   );
        tt.y = (q1C.y - q1A.y) + (q2B.z - q2B.x);
        tt.z = (q1C.z - q1A.z) + (q2B.w - q2B.y);
        tt.w = (q1C.w - q1A.w) + (br    - q2B.z);

        float4 op, ot;
        {
            float at, g, dphi;
            at = atan_pos(GAMMA_ * (TEQ_ - tB.x));
            g = (pB.x * (1.0f - pB.x)) * fmaf(pB.x, DTTAU, fmaf(at, APIXT, MB));
            dphi = fmaf(e2B.x, lapp.x, tt.x) + g;
            op.x = pB.x + dphi; ot.x = fmaf(KAPPA_, dphi, fmaf(DTCI, lapt.x, tB.x));

            at = atan_pos(GAMMA_ * (TEQ_ - tB.y));
            g = (pB.y * (1.0f - pB.y)) * fmaf(pB.y, DTTAU, fmaf(at, APIXT, MB));
            dphi = fmaf(e2B.y, lapp.y, tt.y) + g;
            op.y = pB.y + dphi; ot.y = fmaf(KAPPA_, dphi, fmaf(DTCI, lapt.y, tB.y));

            at = atan_pos(GAMMA_ * (TEQ_ - tB.z));
            g = (pB.z * (1.0f - pB.z)) * fmaf(pB.z, DTTAU, fmaf(at, APIXT, MB));
            dphi = fmaf(e2B.z, lapp.z, tt.z) + g;
            op.z = pB.z + dphi; ot.z = fmaf(KAPPA_, dphi, fmaf(DTCI, lapt.z, tB.z));

            at = atan_pos(GAMMA_ * (TEQ_ - tB.w));
            g = (pB.w * (1.0f - pB.w)) * fmaf(pB.w, DTTAU, fmaf(at, APIXT, MB));
            dphi = fmaf(e2B.w, lapp.w, tt.w) + g;
            op.w = pB.w + dphi; ot.w = fmaf(KAPPA_, dphi, fmaf(DTCI, lapt.w, tB.w));
        }
        const int o = base + (r << 11) + xc;
        __stcs((float4*)(out_phi + o), op);   // streaming: never re-read
        __stcs((float4*)(out_tmp + o), ot);

        // ---- shift windows (prefetched values become current)
        pA = pB; pB = pC; pC = pD; pD = pDn;
        hB = hC; hC = hD; hD = hDn;
        tA = tB; tB = tC; sB = sC; tC = tCn; sC = sCn;
        q1A = q1B; q1B = q1C;
        q2B = q2C; h2B = h2C; e2B = e2C;
        plB = plC; prB = prC;
    }
}

extern "C" void kernel_launch(void* const* d_in, const int* in_sizes, int n_in,
                              void* d_out, int out_size)
{
    const float* phi   = (const float*)d_in[0];
    const float* tempr = (const float*)d_in[1];
    float* out = (float*)d_out;
    float* out_phi = out;
    float* out_tmp = out + (size_t)BATCH * Hd * Wd;

    dim3 block(NWARP * 32);
    dim3 grid(Wd / 128, Hd / VY / NWARP, BATCH);
    dendrite_kernel<<<grid, block>>>(phi, tempr, out_phi, out_tmp);
}

// round 16
// speedup vs baseline: 1.1364x; 1.0336x over previous
#include <cuda_runtime.h>

// Kobayashi dendrite growth, single timestep.
// Register-resident y-sweep, warp-shuffle x-exchange, zero shared memory,
// one-iteration register prefetch + two-row L2 software prefetch.
// Grid/time scales folded; delta-order truncation in aniso (rel err ~4e-5,
// budget 1e-3). B=4, H=W=2048, periodic, fp32. Output: [phi_new | tempr_new].

#define Wd 2048
#define Hd 2048
#define MASK 2047
#define BATCH 4
#define VY 16          // rows per warp strip
#define NWARP 4        // warps per block

// Folded constants:
//  EE1   = EPSB*(-EPSB*ANISO*DELTA)*C_CROSS*DTTAU = -1.1111111e-3
//  NEE1  = -EE1                                   = +1.1111111e-3
//  E2CONST = EPSB^2*INVDX2*DTTAU                  = 3.7037037e-2
//  E2LIN   = 2*DELTA*E2CONST                      = 1.4814815e-3
//  APIXT = (ALPHA/pi)*DTTAU                       = 0.09549297
//  MB    = -0.5*DTTAU                             = -0.16666667
//  DTCI  = DT*INVDX2                              = 0.11111111
#define C6T0    0.3623577545f  // cos(6*0.2)
#define S6T0    0.9320390860f  // sin(6*0.2)
#define EE1     (-1.1111111e-3f)
#define NEE1    (1.1111111e-3f)
#define E2CONST (3.7037037e-2f)
#define E2LIN   (1.4814815e-3f)
#define APIXT   0.09549297f
#define MB      (-0.16666667f)
#define DTTAU   (1.0f/3.0f)
#define DTCI    0.11111111f
#define KAPPA_  1.8f
#define GAMMA_  10.0f
#define TEQ_    1.0f
#define PIO2    1.5707963268f
#define R2PAD   1e-30f

#define FULLM 0xffffffffu

// From raw (unscaled) central differences produce the pre-scaled
//  p1 = sinA*EE1*gx, p2 = -sinA*EE1*gy, e2 = E2CONST + E2LIN*cosA
// (delta-order truncation: ee drops its delta*cosA factor, e2 linearized).
__device__ __forceinline__ void aniso(float gx, float gy,
                                      float& p1, float& p2, float& e2)
{
    float r2 = fmaf(gx, gx, fmaf(gy, gy, R2PAD));
    float inv = rsqrtf(r2);
    float c = gx * inv, s = gy * inv;
    float x2 = c * c;
    float c6 = fmaf(fmaf(fmaf(x2, 32.0f, -48.0f), x2, 18.0f), x2, -1.0f);
    float s6 = (s * c) * fmaf(fmaf(x2, 32.0f, -32.0f), x2, 6.0f);
    float cosA = fmaf(c6, C6T0, s6 * S6T0);
    float sinA = fmaf(s6, C6T0, -c6 * S6T0);
    float ee   = sinA * EE1;
    p1 = ee * gx;
    p2 = -ee * gy;
    e2 = fmaf(cosA, E2LIN, E2CONST);
}

// Strip-edge halo column: only p2 needed (no cosA/e2 chain at all).
__device__ __forceinline__ float aniso_p2(float gx, float gy)
{
    float r2 = fmaf(gx, gx, fmaf(gy, gy, R2PAD));
    float inv = rsqrtf(r2);
    float c = gx * inv, s = gy * inv;
    float x2 = c * c;
    float c6 = fmaf(fmaf(fmaf(x2, 32.0f, -48.0f), x2, 18.0f), x2, -1.0f);
    float s6 = (s * c) * fmaf(fmaf(x2, 32.0f, -32.0f), x2, 6.0f);
    float sinA = fmaf(s6, C6T0, -c6 * S6T0);
    return (sinA * gy) * NEE1;
}

// atan for z >= 0 (arg is GAMMA*(1-T), T in [0,1)). Minimax, err ~2e-7.
__device__ __forceinline__ float atan_pos(float z)
{
    float t = fminf(z, __fdividef(1.0f, z));
    float x2 = t * t;
    float p = fmaf(x2, -0.0117212f, 0.05265332f);
    p = fmaf(p, x2, -0.11643287f);
    p = fmaf(p, x2,  0.19354346f);
    p = fmaf(p, x2, -0.33262347f);
    p = fmaf(p, x2,  0.99997726f);
    p *= t;
    return (z > 1.0f) ? (PIO2 - p) : p;
}

__global__ __launch_bounds__(NWARP * 32, 4)
void dendrite_kernel(const float* __restrict__ phi,
                     const float* __restrict__ tempr,
                     float* __restrict__ out_phi,
                     float* __restrict__ out_tmp)
{
    const int lane = threadIdx.x & 31;
    const int warp = threadIdx.x >> 5;
    const int x0 = blockIdx.x * 128;
    const int y0 = (blockIdx.y * NWARP + warp) * VY;
    const int base = (int)blockIdx.z * (Hd * Wd);
    const float* Pp = phi + base;
    const float* Tp = tempr + base;

    const int xc = x0 + lane * 4;
    const bool eL = (lane == 0);
    const bool eR = (lane == 31);
    const bool edge = eL || eR;
    const int xh2 = eL ? ((x0 - 2) & MASK) : ((x0 + 128) & MASK);
    const int xh1 = eL ? ((x0 - 1) & MASK) : ((x0 + 128) & MASK);

    auto ldP4 = [&](int y) -> float4 {
        return *(const float4*)(Pp + ((y & MASK) << 11) + xc);
    };
    auto ldT4 = [&](int y) -> float4 {
        return *(const float4*)(Tp + ((y & MASK) << 11) + xc);
    };
    auto ldPH = [&](int y) -> float2 {
        float2 h = make_float2(1.0f, 1.0f);
        if (edge) h = *(const float2*)(Pp + ((y & MASK) << 11) + xh2);
        return h;
    };
    auto ldTH = [&](int y) -> float {
        float s = 0.0f;
        if (edge) s = Tp[((y & MASK) << 11) + xh1];
        return s;
    };
    // L2 prefetch: warm DRAM->L2 ahead of the register loads (no data regs).
    auto pfL2 = [&](const float* p, int y) {
        asm volatile("prefetch.global.L2 [%0];"
                     :: "l"(p + ((y & MASK) << 11) + xc));
    };

    // aniso over one row; h2 = halo-column p2; plc/prc = the center row's
    // left/right phi neighbors (re-used by the output stage next iteration).
    auto aniso_row = [&](const float4& pm, const float4& pc, const float4& pp,
                         const float2& hm, const float2& hc, const float2& hp,
                         float4& q1, float4& q2, float4& e2v, float& h2,
                         float& plc, float& prc)
    {
        float pl = __shfl_up_sync(FULLM, pc.w, 1);
        if (eL) pl = hc.y;
        float pr = __shfl_down_sync(FULLM, pc.x, 1);
        if (eR) pr = hc.x;
        aniso(pc.y - pl,   pp.x - pm.x, q1.x, q2.x, e2v.x);
        aniso(pc.z - pc.x, pp.y - pm.y, q1.y, q2.y, e2v.y);
        aniso(pc.w - pc.y, pp.z - pm.z, q1.z, q2.z, e2v.z);
        aniso(pr - pc.z,   pp.w - pm.w, q1.w, q2.w, e2v.w);
        float gxh = eL ? (pc.x - hc.x) : (hc.y - pc.w);
        float gyh = eL ? (hp.y - hm.y) : (hp.x - hm.x);
        h2 = aniso_p2(gxh, gyh);
        plc = pl; prc = pr;
    };

    // ---- prologue: windows for rows y0-1 .. y0+1
    float4 pZ = ldP4(y0 - 2);
    float4 pA = ldP4(y0 - 1);  float2 hA = ldPH(y0 - 1);
    float4 pB = ldP4(y0);      float2 hB = ldPH(y0);
    float4 pC = ldP4(y0 + 1);  float2 hC = ldPH(y0 + 1);
    float4 tA = ldT4(y0 - 1);
    float4 tB = ldT4(y0);      float  sB = ldTH(y0);

    // prefetched values consumed by the FIRST loop iteration
    float4 pD = ldP4(y0 + 2);  float2 hD = ldPH(y0 + 2);
    float4 tC = ldT4(y0 + 1);  float  sC = ldTH(y0 + 1);

    // warm L2 for the first loop iterations' register loads
    pfL2(Pp, y0 + 3);
    pfL2(Pp, y0 + 4);
    pfL2(Tp, y0 + 2);
    pfL2(Tp, y0 + 3);

    float4 q1A, q2A, e2A; float h2A, plA, prA;   // row y0-1 (only q1A consumed)
    aniso_row(pZ, pA, pB, hA, hA, hA, q1A, q2A, e2A, h2A, plA, prA);
    float4 q1B, q2B, e2B; float h2B, plB, prB;   // row y0
    aniso_row(pA, pB, pC, hA, hB, hC, q1B, q2B, e2B, h2B, plB, prB);

    #pragma unroll 4
    for (int r = y0; r < y0 + VY; ++r) {
        // ---- L2 prefetch two rows beyond next iteration's register loads
        pfL2(Pp, r + 5);
        pfL2(Tp, r + 4);

        // ---- register prefetch for NEXT iteration (consumed after shift);
        //      last iteration's extra rows wrap harmlessly.
        float4 pDn = ldP4(r + 3);  float2 hDn = ldPH(r + 3);
        float4 tCn = ldT4(r + 2);  float  sCn = ldTH(r + 2);

        float4 q1C, q2C, e2C; float h2C, plC, prC;   // row r+1
        aniso_row(pB, pC, pD, hB, hC, hD, q1C, q2C, e2C, h2C, plC, prC);

        // ---- output at row r (pl/pr carried from row r's aniso_row)
        float tl = __shfl_up_sync(FULLM, tB.w, 1);   if (eL) tl = sB;
        float tr = __shfl_down_sync(FULLM, tB.x, 1); if (eR) tr = sB;
        float bl = __shfl_up_sync(FULLM, q2B.w, 1);  if (eL) bl = h2B;
        float br = __shfl_down_sync(FULLM, q2B.x, 1); if (eR) br = h2B;

        // raw 5-point sums; all scales pre-folded into e2/DTCI/tt terms
        float4 lapp, lapt, tt;
        lapp.x = fmaf(-4.0f, pB.x, pA.x + pC.x + plB  + pB.y);
        lapp.y = fmaf(-4.0f, pB.y, pA.y + pC.y + pB.x + pB.z);
        lapp.z = fmaf(-4.0f, pB.z, pA.z + pC.z + pB.y + pB.w);
        lapp.w = fmaf(-4.0f, pB.w, pA.w + pC.w + pB.z + prB );

        lapt.x = fmaf(-4.0f, tB.x, tA.x + tC.x + tl   + tB.y);
        lapt.y = fmaf(-4.0f, tB.y, tA.y + tC.y + tB.x + tB.z);
        lapt.z = fmaf(-4.0f, tB.z, tA.z + tC.z + tB.y + tB.w);
        lapt.w = fmaf(-4.0f, tB.w, tA.w + tC.w + tB.z + tr  );

        tt.x = (q1C.x - q1A.x) + (q2B.y - bl   );
        tt.y = (q1C.y - q1A.y) + (q2B.z - q2B.x);
        tt.z = (q1C.z - q1A.z) + (q2B.w - q2B.y);
        tt.w = (q1C.w - q1A.w) + (br    - q2B.z);

        float4 op, ot;
        {
            float at, g, dphi;
            at = atan_pos(GAMMA_ * (TEQ_ - tB.x));
            g = (pB.x * (1.0f - pB.x)) * fmaf(pB.x, DTTAU, fmaf(at, APIXT, MB));
            dphi = fmaf(e2B.x, lapp.x, tt.x) + g;
            op.x = pB.x + dphi; ot.x = fmaf(KAPPA_, dphi, fmaf(DTCI, lapt.x, tB.x));

            at = atan_pos(GAMMA_ * (TEQ_ - tB.y));
            g = (pB.y * (1.0f - pB.y)) * fmaf(pB.y, DTTAU, fmaf(at, APIXT, MB));
            dphi = fmaf(e2B.y, lapp.y, tt.y) + g;
            op.y = pB.y + dphi; ot.y = fmaf(KAPPA_, dphi, fmaf(DTCI, lapt.y, tB.y));

            at = atan_pos(GAMMA_ * (TEQ_ - tB.z));
            g = (pB.z * (1.0f - pB.z)) * fmaf(pB.z, DTTAU, fmaf(at, APIXT, MB));
            dphi = fmaf(e2B.z, lapp.z, tt.z) + g;
            op.z = pB.z + dphi; ot.z = fmaf(KAPPA_, dphi, fmaf(DTCI, lapt.z, tB.z));

            at = atan_pos(GAMMA_ * (TEQ_ - tB.w));
            g = (pB.w * (1.0f - pB.w)) * fmaf(pB.w, DTTAU, fmaf(at, APIXT, MB));
            dphi = fmaf(e2B.w, lapp.w, tt.w) + g;
            op.w = pB.w + dphi; ot.w = fmaf(KAPPA_, dphi, fmaf(DTCI, lapt.w, tB.w));
        }
        const int o = base + (r << 11) + xc;
        __stcs((float4*)(out_phi + o), op);   // streaming: never re-read
        __stcs((float4*)(out_tmp + o), ot);

        // ---- shift windows (prefetched values become current)
        pA = pB; pB = pC; pC = pD; pD = pDn;
        hB = hC; hC = hD; hD = hDn;
        tA = tB; tB = tC; sB = sC; tC = tCn; sC = sCn;
        q1A = q1B; q1B = q1C;
        q2B = q2C; h2B = h2C; e2B = e2C;
        plB = plC; prB = prC;
    }
}

extern "C" void kernel_launch(void* const* d_in, const int* in_sizes, int n_in,
                              void* d_out, int out_size)
{
    const float* phi   = (const float*)d_in[0];
    const float* tempr = (const float*)d_in[1];
    float* out = (float*)d_out;
    float* out_phi = out;
    float* out_tmp = out + (size_t)BATCH * Hd * Wd;

    dim3 block(NWARP * 32);
    dim3 grid(Wd / 128, Hd / VY / NWARP, BATCH);
    dendrite_kernel<<<grid, block>>>(phi, tempr, out_phi, out_tmp);
}